// round 1
// baseline (speedup 1.0000x reference)
#include <cuda_runtime.h>
#include <cuda_bf16.h>

// Problem constants (fixed by the dataset)
#define N_NODES   50000
#define F_IN      256
#define F_OUT     64
#define N_EDGES   1600000
#define ALPHA     0.2f

// Scratch (static device globals; no allocation allowed)
__device__ float g_Wh[N_NODES * F_OUT];      // 12.8 MB
__device__ float g_accum[N_NODES * F_OUT];   // 12.8 MB
__device__ float g_ssrc[N_NODES];
__device__ float g_sdst[N_NODES];
__device__ float g_rowsum[N_NODES];

// ---------------------------------------------------------------------------
// Kernel 1: Wh = x @ W   (classic smem-tiled fp32 GEMM, BM=64 BN=64 BK=32)
// ---------------------------------------------------------------------------
#define BM 64
#define BN 64
#define BK 32

__global__ __launch_bounds__(256) void gemm_kernel(
    const float* __restrict__ x, const float* __restrict__ W,
    float* __restrict__ Wh, int nrows)
{
    __shared__ float As[BK][BM + 1];   // stored transposed: As[k][m]
    __shared__ float Bs[BK][BN];

    const int block_row = blockIdx.x * BM;
    const int tid = threadIdx.x;
    const int tr = (tid / 16) * 4;     // row offset of 4x4 micro-tile
    const int tc = (tid % 16) * 4;     // col offset

    float acc[4][4] = {};

    for (int k0 = 0; k0 < F_IN; k0 += BK) {
        // Load A tile: 64 rows x 32 cols = 512 float4, 2 per thread
        #pragma unroll
        for (int i = 0; i < 2; i++) {
            int idx = tid + i * 256;           // 0..511
            int m   = idx >> 3;                // 8 float4 per row
            int kk  = (idx & 7) * 4;
            int gm  = block_row + m;
            float4 v = make_float4(0.f, 0.f, 0.f, 0.f);
            if (gm < nrows)
                v = *reinterpret_cast<const float4*>(x + (size_t)gm * F_IN + k0 + kk);
            As[kk + 0][m] = v.x;
            As[kk + 1][m] = v.y;
            As[kk + 2][m] = v.z;
            As[kk + 3][m] = v.w;
        }
        // Load B tile: 32 x 64 = 512 float4, 2 per thread
        #pragma unroll
        for (int i = 0; i < 2; i++) {
            int idx = tid + i * 256;
            int kk  = idx >> 4;                // 16 float4 per row
            int n   = (idx & 15) * 4;
            *reinterpret_cast<float4*>(&Bs[kk][n]) =
                *reinterpret_cast<const float4*>(W + (size_t)(k0 + kk) * F_OUT + n);
        }
        __syncthreads();

        #pragma unroll
        for (int k = 0; k < BK; k++) {
            float a0 = As[k][tr + 0];
            float a1 = As[k][tr + 1];
            float a2 = As[k][tr + 2];
            float a3 = As[k][tr + 3];
            float4 b = *reinterpret_cast<float4*>(&Bs[k][tc]);
            acc[0][0] += a0 * b.x; acc[0][1] += a0 * b.y; acc[0][2] += a0 * b.z; acc[0][3] += a0 * b.w;
            acc[1][0] += a1 * b.x; acc[1][1] += a1 * b.y; acc[1][2] += a1 * b.z; acc[1][3] += a1 * b.w;
            acc[2][0] += a2 * b.x; acc[2][1] += a2 * b.y; acc[2][2] += a2 * b.z; acc[2][3] += a2 * b.w;
            acc[3][0] += a3 * b.x; acc[3][1] += a3 * b.y; acc[3][2] += a3 * b.z; acc[3][3] += a3 * b.w;
        }
        __syncthreads();
    }

    #pragma unroll
    for (int i = 0; i < 4; i++) {
        int m = block_row + tr + i;
        if (m < nrows) {
            *reinterpret_cast<float4*>(Wh + (size_t)m * F_OUT + tc) =
                make_float4(acc[i][0], acc[i][1], acc[i][2], acc[i][3]);
        }
    }
}

// ---------------------------------------------------------------------------
// Kernel 2: per-node scores s_src = Wh . a[:64], s_dst = Wh . a[64:]
// one warp per row
// ---------------------------------------------------------------------------
__global__ __launch_bounds__(256) void score_kernel(
    const float* __restrict__ Wh, const float* __restrict__ a,
    float* __restrict__ ssrc, float* __restrict__ sdst, int nrows)
{
    int row  = blockIdx.x * 8 + (threadIdx.x >> 5);
    int lane = threadIdx.x & 31;
    if (row >= nrows) return;

    const float* wr = Wh + (size_t)row * F_OUT;
    float v0 = wr[lane], v1 = wr[lane + 32];
    float p = v0 * a[lane]      + v1 * a[lane + 32];
    float q = v0 * a[64 + lane] + v1 * a[96 + lane];
    #pragma unroll
    for (int o = 16; o; o >>= 1) {
        p += __shfl_xor_sync(0xffffffffu, p, o);
        q += __shfl_xor_sync(0xffffffffu, q, o);
    }
    if (lane == 0) { ssrc[row] = p; sdst[row] = q; }
}

// ---------------------------------------------------------------------------
// Kernel 3: zero accumulators
// ---------------------------------------------------------------------------
__global__ void zero_kernel(float* __restrict__ accum, float* __restrict__ rowsum, int nrows)
{
    int i = blockIdx.x * blockDim.x + threadIdx.x;           // float4 index
    int n4 = nrows * (F_OUT / 4);
    if (i < n4)
        reinterpret_cast<float4*>(accum)[i] = make_float4(0.f, 0.f, 0.f, 0.f);
    if (i < nrows)
        rowsum[i] = 0.f;
}

// ---------------------------------------------------------------------------
// Kernel 4: edge aggregation.  8 threads per edge; each handles 8 floats
// (2 x float4) of Wh[dst], scaled by edge weight, reduced into accum[src].
// ---------------------------------------------------------------------------
__device__ __forceinline__ void red_add_v4(float* addr, float4 v)
{
    asm volatile("red.global.add.v4.f32 [%0], {%1, %2, %3, %4};"
                 :: "l"(addr), "f"(v.x), "f"(v.y), "f"(v.z), "f"(v.w)
                 : "memory");
}

__global__ __launch_bounds__(256) void edge_kernel(
    const int* __restrict__ src, const int* __restrict__ dst,
    const float* __restrict__ ssrc, const float* __restrict__ sdst,
    const float* __restrict__ Wh,
    float* __restrict__ accum, float* __restrict__ rowsum, int nedges)
{
    int g = blockIdx.x * blockDim.x + threadIdx.x;
    int e = g >> 3;          // edge index
    int t = g & 7;           // sub-thread within edge
    if (e >= nedges) return;

    int s = __ldg(src + e);
    int d = __ldg(dst + e);

    float score = __ldg(ssrc + s) + __ldg(sdst + d);
    float l = score > 0.f ? score : ALPHA * score;
    float w = __expf(-l);

    if (t == 0)
        atomicAdd(rowsum + s, w);

    const float4* whp = reinterpret_cast<const float4*>(Wh + (size_t)d * F_OUT) + t * 2;
    float4 v0 = __ldg(whp + 0);
    float4 v1 = __ldg(whp + 1);
    v0.x *= w; v0.y *= w; v0.z *= w; v0.w *= w;
    v1.x *= w; v1.y *= w; v1.z *= w; v1.w *= w;

    float* ap = accum + (size_t)s * F_OUT + t * 8;
    red_add_v4(ap + 0, v0);
    red_add_v4(ap + 4, v1);
}

// ---------------------------------------------------------------------------
// Kernel 5: finalize: out = ELU(accum / rowsum)
// ---------------------------------------------------------------------------
__global__ void finalize_kernel(
    const float* __restrict__ accum, const float* __restrict__ rowsum,
    float* __restrict__ out, int nrows)
{
    int i = blockIdx.x * blockDim.x + threadIdx.x;   // float4 index
    int n4 = nrows * (F_OUT / 4);
    if (i >= n4) return;
    int row = i >> 4;                                // 16 float4 per row
    float inv = 1.0f / rowsum[row];
    float4 v = reinterpret_cast<const float4*>(accum)[i];
    v.x *= inv; v.y *= inv; v.z *= inv; v.w *= inv;
    v.x = v.x > 0.f ? v.x : expm1f(v.x);
    v.y = v.y > 0.f ? v.y : expm1f(v.y);
    v.z = v.z > 0.f ? v.z : expm1f(v.z);
    v.w = v.w > 0.f ? v.w : expm1f(v.w);
    reinterpret_cast<float4*>(out)[i] = v;
}

// ---------------------------------------------------------------------------
// Launch
// ---------------------------------------------------------------------------
extern "C" void kernel_launch(void* const* d_in, const int* in_sizes, int n_in,
                              void* d_out, int out_size)
{
    const float* x    = (const float*)d_in[0];
    const int*   edge = (const int*)d_in[1];
    const float* W    = (const float*)d_in[2];
    const float* a    = (const float*)d_in[3];
    float*       out  = (float*)d_out;

    const int nrows  = in_sizes[0] / F_IN;     // 50000
    const int nedges = in_sizes[1] / 2;        // 1600000
    const int* src = edge;
    const int* dst = edge + nedges;

    float *Wh, *accum, *ssrc, *sdst, *rowsum;
    cudaGetSymbolAddress((void**)&Wh,     g_Wh);
    cudaGetSymbolAddress((void**)&accum,  g_accum);
    cudaGetSymbolAddress((void**)&ssrc,   g_ssrc);
    cudaGetSymbolAddress((void**)&sdst,   g_sdst);
    cudaGetSymbolAddress((void**)&rowsum, g_rowsum);

    // 1. GEMM
    int gblocks = (nrows + BM - 1) / BM;
    gemm_kernel<<<gblocks, 256>>>(x, W, Wh, nrows);

    // 2. node scores
    score_kernel<<<(nrows + 7) / 8, 256>>>(Wh, a, ssrc, sdst, nrows);

    // 3. zero accumulators
    int n4 = nrows * (F_OUT / 4);
    zero_kernel<<<(n4 + 255) / 256, 256>>>(accum, rowsum, nrows);

    // 4. edge aggregation (8 threads / edge)
    long long tot = (long long)nedges * 8;
    edge_kernel<<<(int)((tot + 255) / 256), 256>>>(src, dst, ssrc, sdst, Wh,
                                                    accum, rowsum, nedges);

    // 5. finalize
    finalize_kernel<<<(n4 + 255) / 256, 256>>>(accum, rowsum, out, nrows);
}